// round 13
// baseline (speedup 1.0000x reference)
#include <cuda_runtime.h>
#include <cuda_bf16.h>
#include <cuda_fp8.h>
#include <math.h>
#include <stdint.h>

#define NN 100000
#define EE 1600000
#define CH0 50048
#define CH1 (NN - CH0)
#define SCAN_NB ((NN + 1023) / 1024)

// ---------------- static scratch ----------------
__device__ float g_bufA[(size_t)NN * 256];
__device__ float g_bufB[(size_t)NN * 256];
__device__ float g_bufC[(size_t)NN * 256];
__device__ float g_sout[NN];
__device__ float g_sin[NN];
__device__ int   g_cnt_out[NN];
__device__ int   g_cnt_in[NN];
__device__ int   g_cursor[NN];
__device__ int   g_row_ptr[NN + 1];
__device__ int   g_csr[EE];
__device__ int   g_blocksum[128];
__device__ float g_wt[6][65536];

// ---------------- graph preprocessing ----------------
__global__ void k_zero_counts() {
    int i = blockIdx.x * blockDim.x + threadIdx.x;
    if (i < NN) { g_cnt_out[i] = 0; g_cnt_in[i] = 0; g_cursor[i] = 0; }
}
__global__ void k_hist(const int* __restrict__ src, const int* __restrict__ dst) {
    int stride = gridDim.x * blockDim.x;
    for (int i = blockIdx.x * blockDim.x + threadIdx.x; i < EE; i += stride) {
        atomicAdd(&g_cnt_out[src[i]], 1);
        atomicAdd(&g_cnt_in[dst[i]], 1);
    }
}
__global__ void k_scan1() {
    __shared__ int wsum[32];
    int b = blockIdx.x, t = threadIdx.x, lane = t & 31, w = t >> 5;
    int idx = b * 1024 + t;
    int x = (idx < NN) ? g_cnt_in[idx] : 0;
#pragma unroll
    for (int off = 1; off < 32; off <<= 1) {
        int y = __shfl_up_sync(0xffffffffu, x, off);
        if (lane >= off) x += y;
    }
    if (lane == 31) wsum[w] = x;
    __syncthreads();
    if (w == 0) {
        int s = wsum[lane];
#pragma unroll
        for (int off = 1; off < 32; off <<= 1) {
            int y = __shfl_up_sync(0xffffffffu, s, off);
            if (lane >= off) s += y;
        }
        wsum[lane] = s;
    }
    __syncthreads();
    int res = ((w > 0) ? wsum[w - 1] : 0) + x;
    if (idx < NN) g_row_ptr[idx + 1] = res;
    if (t == 1023) g_blocksum[b] = res;
}
__global__ void k_scan2() {
    __shared__ int wsum[4];
    int t = threadIdx.x, lane = t & 31, w = t >> 5;
    int v = (t < SCAN_NB) ? g_blocksum[t] : 0;
    int x = v;
#pragma unroll
    for (int off = 1; off < 32; off <<= 1) {
        int y = __shfl_up_sync(0xffffffffu, x, off);
        if (lane >= off) x += y;
    }
    if (lane == 31) wsum[w] = x;
    __syncthreads();
    if (t == 0) {
        int c = 0;
        for (int i = 0; i < 4; i++) { int tmp = wsum[i]; wsum[i] = c; c += tmp; }
    }
    __syncthreads();
    if (t < SCAN_NB) g_blocksum[t] = wsum[w] + x - v;
}
__global__ void k_scan3() {
    int b = blockIdx.x, t = threadIdx.x;
    int idx = b * 1024 + t;
    if (idx == 0) g_row_ptr[0] = 0;
    if (idx < NN && b > 0) g_row_ptr[idx + 1] += g_blocksum[b];
}
__global__ void k_fill(const int* __restrict__ src, const int* __restrict__ dst) {
    int stride = gridDim.x * blockDim.x;
    for (int i = blockIdx.x * blockDim.x + threadIdx.x; i < EE; i += stride) {
        int d = dst[i];
        int pos = g_row_ptr[d] + atomicAdd(&g_cursor[d], 1);
        g_csr[pos] = src[i];
    }
}
__global__ void k_scales() {
    int i = blockIdx.x * blockDim.x + threadIdx.x;
    if (i < NN) {
        g_sout[i] = rsqrtf(fmaxf((float)g_cnt_out[i], 1.f));
        g_sin[i]  = rsqrtf(fmaxf((float)g_cnt_in[i], 1.f));
    }
}

__global__ void k_transpose_all(
    const float* W0, const float* W1, const float* W2,
    const float* W3, const float* W4, const float* W5,
    __nv_bfloat16* T0, __nv_bfloat16* T1, __nv_bfloat16* T2,
    __nv_bfloat16* T3, __nv_bfloat16* T4, __nv_bfloat16* T5) {
    __shared__ float t[32][33];
    const float* W; __nv_bfloat16* WT; int K, N;
    switch (blockIdx.z) {
        case 0: W = W0; WT = T0; K = 128; N = 256; break;
        case 1: W = W1; WT = T1; K = 256; N = 256; break;
        case 2: W = W2; WT = T2; K = 256; N = 128; break;
        case 3: W = W3; WT = T3; K = 128; N = 256; break;
        case 4: W = W4; WT = T4; K = 256; N = 256; break;
        default: W = W5; WT = T5; K = 256; N = 128; break;
    }
    int k0 = blockIdx.x * 32, n0 = blockIdx.y * 32;
    if (k0 >= K || n0 >= N) return;
    int x = threadIdx.x, y = threadIdx.y;
    for (int i = 0; i < 32; i += 8) {
        int k = k0 + y + i, n = n0 + x;
        t[y + i][x] = (k < K && n < N) ? W[(size_t)k * N + n] : 0.f;
    }
    __syncthreads();
    for (int i = 0; i < 32; i += 8) {
        int n = n0 + y + i, k = k0 + x;
        if (n < N && k < K) WT[(size_t)n * K + k] = __float2bfloat16(t[x][y + i]);
    }
}

// ---------------- fp8 helpers ----------------
__device__ __forceinline__ void acc_add_f8(float4& a, uint32_t v) {
    __half2_raw h0 = __nv_cvt_fp8x2_to_halfraw2((__nv_fp8x2_storage_t)(v & 0xffffu), __NV_E4M3);
    __half2_raw h1 = __nv_cvt_fp8x2_to_halfraw2((__nv_fp8x2_storage_t)(v >> 16), __NV_E4M3);
    float2 f0 = __half22float2(*(__half2*)&h0);
    float2 f1 = __half22float2(*(__half2*)&h1);
    a.x += f0.x; a.y += f0.y; a.z += f1.x; a.w += f1.y;
}
__device__ __forceinline__ unsigned short f2_to_f8x2(float ox, float oy) {
    return (unsigned short)__nv_cvt_float2_to_fp8x2(make_float2(ox, oy), __NV_SATFINITE, __NV_E4M3);
}

// prescale in_feat by sout -> fp8
__global__ void k_prescale_f8(const float* __restrict__ x, uint8_t* __restrict__ o) {
    int i = blockIdx.x * blockDim.x + threadIdx.x;   // one float4 -> 4 fp8
    if (i >= NN * 32) return;
    int m = i >> 5;
    float s = g_sout[m];
    float4 v = ((const float4*)x)[i];
    uint32_t r = (uint32_t)f2_to_f8x2(v.x * s, v.y * s) |
                 ((uint32_t)f2_to_f8x2(v.z * s, v.w * s) << 16);
    ((uint32_t*)o)[i] = r;
}

// ---------------- fp8-input aggregation (fp32 accumulate, bf16 out) ----------------
// D=128: one uint32 (4 fp8) per lane per edge; 4 gathers in flight
__global__ void k_agg_f8_128(const uint8_t* __restrict__ x, __nv_bfloat16* __restrict__ out,
                             int n0, int ncnt) {
    int wloc = (blockIdx.x * blockDim.x + threadIdx.x) >> 5;
    int lane = threadIdx.x & 31;
    if (wloc >= ncnt) return;
    int node = n0 + wloc;
    int s0 = g_row_ptr[node], s1 = g_row_ptr[node + 1];
    float4 a0 = make_float4(0.f, 0.f, 0.f, 0.f);
    float4 a1 = make_float4(0.f, 0.f, 0.f, 0.f);
    float4 a2 = make_float4(0.f, 0.f, 0.f, 0.f);
    float4 a3 = make_float4(0.f, 0.f, 0.f, 0.f);
    for (int base = s0; base < s1; base += 32) {
        int cnt = min(32, s1 - base);
        int myidx = (lane < cnt) ? g_csr[base + lane] : 0;
        int e = 0;
        for (; e + 4 <= cnt; e += 4) {
            int sa = __shfl_sync(0xffffffffu, myidx, e);
            int sb = __shfl_sync(0xffffffffu, myidx, e + 1);
            int sc = __shfl_sync(0xffffffffu, myidx, e + 2);
            int sd = __shfl_sync(0xffffffffu, myidx, e + 3);
            uint32_t va = ((const uint32_t*)(x + (size_t)sa * 128))[lane];
            uint32_t vb = ((const uint32_t*)(x + (size_t)sb * 128))[lane];
            uint32_t vc = ((const uint32_t*)(x + (size_t)sc * 128))[lane];
            uint32_t vd = ((const uint32_t*)(x + (size_t)sd * 128))[lane];
            acc_add_f8(a0, va); acc_add_f8(a1, vb); acc_add_f8(a2, vc); acc_add_f8(a3, vd);
        }
        for (; e < cnt; e++) {
            int sa = __shfl_sync(0xffffffffu, myidx, e);
            acc_add_f8(a0, ((const uint32_t*)(x + (size_t)sa * 128))[lane]);
        }
    }
    float4 acc = make_float4(a0.x + a1.x + a2.x + a3.x, a0.y + a1.y + a2.y + a3.y,
                             a0.z + a1.z + a2.z + a3.z, a0.w + a1.w + a2.w + a3.w);
    uint2 r;
    __nv_bfloat162 p0 = __float22bfloat162_rn(make_float2(acc.x, acc.y));
    __nv_bfloat162 p1 = __float22bfloat162_rn(make_float2(acc.z, acc.w));
    r.x = *(uint32_t*)&p0; r.y = *(uint32_t*)&p1;
    ((uint2*)out)[(size_t)node * 32 + lane] = r;
}

// D=256: one uint2 (8 fp8) per lane per edge; 2 gathers in flight
__global__ void k_agg_f8_256(const uint8_t* __restrict__ x, __nv_bfloat16* __restrict__ out,
                             int n0, int ncnt) {
    int wloc = (blockIdx.x * blockDim.x + threadIdx.x) >> 5;
    int lane = threadIdx.x & 31;
    if (wloc >= ncnt) return;
    int node = n0 + wloc;
    int s0 = g_row_ptr[node], s1 = g_row_ptr[node + 1];
    float4 a0 = make_float4(0.f, 0.f, 0.f, 0.f), a1 = make_float4(0.f, 0.f, 0.f, 0.f);
    float4 b0 = make_float4(0.f, 0.f, 0.f, 0.f), b1 = make_float4(0.f, 0.f, 0.f, 0.f);
    for (int base = s0; base < s1; base += 32) {
        int cnt = min(32, s1 - base);
        int myidx = (lane < cnt) ? g_csr[base + lane] : 0;
        int e = 0;
        for (; e + 2 <= cnt; e += 2) {
            int sa = __shfl_sync(0xffffffffu, myidx, e);
            int sb = __shfl_sync(0xffffffffu, myidx, e + 1);
            uint2 va = ((const uint2*)(x + (size_t)sa * 256))[lane];
            uint2 vb = ((const uint2*)(x + (size_t)sb * 256))[lane];
            acc_add_f8(a0, va.x); acc_add_f8(a1, va.y);
            acc_add_f8(b0, vb.x); acc_add_f8(b1, vb.y);
        }
        if (e < cnt) {
            int sa = __shfl_sync(0xffffffffu, myidx, e);
            uint2 va = ((const uint2*)(x + (size_t)sa * 256))[lane];
            acc_add_f8(a0, va.x); acc_add_f8(a1, va.y);
        }
    }
    a0.x += b0.x; a0.y += b0.y; a0.z += b0.z; a0.w += b0.w;
    a1.x += b1.x; a1.y += b1.y; a1.z += b1.z; a1.w += b1.w;
    uint4 r;
    __nv_bfloat162 q0 = __float22bfloat162_rn(make_float2(a0.x, a0.y));
    __nv_bfloat162 q1 = __float22bfloat162_rn(make_float2(a0.z, a0.w));
    __nv_bfloat162 q2 = __float22bfloat162_rn(make_float2(a1.x, a1.y));
    __nv_bfloat162 q3 = __float22bfloat162_rn(make_float2(a1.z, a1.w));
    r.x = *(uint32_t*)&q0; r.y = *(uint32_t*)&q1;
    r.z = *(uint32_t*)&q2; r.w = *(uint32_t*)&q3;
    ((uint4*)out)[(size_t)node * 32 + lane] = r;
}

// ---------------- bf16-input aggregation (conv3 V) + fused softmax ----------------
__device__ __forceinline__ void acc_add2(float4& a, uint2 v) {
    __nv_bfloat162 p0 = *(__nv_bfloat162*)&v.x;
    __nv_bfloat162 p1 = *(__nv_bfloat162*)&v.y;
    a.x += __low2float(p0); a.y += __high2float(p0);
    a.z += __low2float(p1); a.w += __high2float(p1);
}
__device__ __forceinline__ float4 agg128_core(const __nv_bfloat16* __restrict__ x,
                                              int s0, int s1, int lane) {
    float4 a0 = make_float4(0.f, 0.f, 0.f, 0.f);
    float4 a1 = make_float4(0.f, 0.f, 0.f, 0.f);
    float4 a2 = make_float4(0.f, 0.f, 0.f, 0.f);
    float4 a3 = make_float4(0.f, 0.f, 0.f, 0.f);
    for (int base = s0; base < s1; base += 32) {
        int cnt = min(32, s1 - base);
        int myidx = (lane < cnt) ? g_csr[base + lane] : 0;
        int e = 0;
        for (; e + 4 <= cnt; e += 4) {
            int sa = __shfl_sync(0xffffffffu, myidx, e);
            int sb = __shfl_sync(0xffffffffu, myidx, e + 1);
            int sc = __shfl_sync(0xffffffffu, myidx, e + 2);
            int sd = __shfl_sync(0xffffffffu, myidx, e + 3);
            uint2 va = ((const uint2*)(x + (size_t)sa * 128))[lane];
            uint2 vb = ((const uint2*)(x + (size_t)sb * 128))[lane];
            uint2 vc = ((const uint2*)(x + (size_t)sc * 128))[lane];
            uint2 vd = ((const uint2*)(x + (size_t)sd * 128))[lane];
            acc_add2(a0, va); acc_add2(a1, vb); acc_add2(a2, vc); acc_add2(a3, vd);
        }
        for (; e < cnt; e++) {
            int sa = __shfl_sync(0xffffffffu, myidx, e);
            uint2 va = ((const uint2*)(x + (size_t)sa * 128))[lane];
            acc_add2(a0, va);
        }
    }
    return make_float4(a0.x + a1.x + a2.x + a3.x, a0.y + a1.y + a2.y + a3.y,
                       a0.z + a1.z + a2.z + a3.z, a0.w + a1.w + a2.w + a3.w);
}

__global__ void k_agg_smax128(const __nv_bfloat16* __restrict__ x,
                              float* __restrict__ out, __nv_bfloat16* __restrict__ outb,
                              const float* __restrict__ rowscale, const float* __restrict__ bias,
                              int n0, int ncnt) {
    int wloc = (blockIdx.x * blockDim.x + threadIdx.x) >> 5;
    int lane = threadIdx.x & 31;
    if (wloc >= ncnt) return;
    int node = n0 + wloc;
    int s0 = g_row_ptr[node], s1 = g_row_ptr[node + 1];
    float4 v = agg128_core(x, s0, s1, lane);
    float rs = rowscale[node];
    float4 b = ((const float4*)bias)[lane];
    v.x = v.x * rs + b.x; v.y = v.y * rs + b.y;
    v.z = v.z * rs + b.z; v.w = v.w * rs + b.w;
    float m = fmaxf(fmaxf(v.x, v.y), fmaxf(v.z, v.w));
#pragma unroll
    for (int off = 16; off > 0; off >>= 1) m = fmaxf(m, __shfl_xor_sync(0xffffffffu, m, off));
    v.x = expf(v.x - m); v.y = expf(v.y - m);
    v.z = expf(v.z - m); v.w = expf(v.w - m);
    float s = v.x + v.y + v.z + v.w;
#pragma unroll
    for (int off = 16; off > 0; off >>= 1) s += __shfl_xor_sync(0xffffffffu, s, off);
    float inv = 1.f / s;
    v.x *= inv; v.y *= inv; v.z *= inv; v.w *= inv;
    ((float4*)out)[(size_t)node * 32 + lane] = v;
    uint2 r;
    __nv_bfloat162 p0 = __float22bfloat162_rn(make_float2(v.x, v.y));
    __nv_bfloat162 p1 = __float22bfloat162_rn(make_float2(v.z, v.w));
    r.x = *(uint32_t*)&p0; r.y = *(uint32_t*)&p1;
    ((uint2*)outb)[(size_t)node * 32 + lane] = r;
}

// ---------------- bf16 tensor-core GEMM, BN=128, cp.async 2-stage ----------------
__device__ __forceinline__ void mma_bf16(float* d, const uint32_t* a, const uint32_t* b) {
    asm volatile(
        "mma.sync.aligned.m16n8k16.row.col.f32.bf16.bf16.f32 "
        "{%0,%1,%2,%3}, {%4,%5,%6,%7}, {%8,%9}, {%0,%1,%2,%3};"
        : "+f"(d[0]), "+f"(d[1]), "+f"(d[2]), "+f"(d[3])
        : "r"(a[0]), "r"(a[1]), "r"(a[2]), "r"(a[3]), "r"(b[0]), "r"(b[1]));
}
__device__ __forceinline__ void cp16(uint32_t dst, const void* src, int sz) {
    asm volatile("cp.async.cg.shared.global [%0], [%1], 16, %2;" :: "r"(dst), "l"(src), "r"(sz) : "memory");
}
#define CP_COMMIT() asm volatile("cp.async.commit_group;" ::: "memory")

// ACT: 0 none, 1 tanh, 2 row-softmax (N==128, gridDim.y==1, OUTT=0)
// OUTT: 0 fp32, 1 bf16, 2 fp8
template <int ACT, int OUTT>
__global__ void __launch_bounds__(256, 2)
k_gemm_bf16(const __nv_bfloat16* __restrict__ A, const __nv_bfloat16* __restrict__ WT,
            void* __restrict__ Cout, int M, int K, int N,
            const float* __restrict__ prescale, const float* __restrict__ bias,
            const float* __restrict__ postscale) {
    extern __shared__ __nv_bfloat16 sm[];
    constexpr int AW = 128 * 72;
    constexpr int BW = 128 * 72;
    __nv_bfloat16* As = sm;
    __nv_bfloat16* Bs = sm + 2 * AW;
    uint32_t sA = (uint32_t)__cvta_generic_to_shared(As);
    uint32_t sB = (uint32_t)__cvta_generic_to_shared(Bs);

    int tid = threadIdx.x;
    int warp = tid >> 5, lane = tid & 31;
    int g = lane >> 2, t = lane & 3;
    int wm = warp >> 1, wn = warp & 1;
    int bm = blockIdx.x * 128, bn = blockIdx.y * 128;
    int lrow = tid >> 3, lq = tid & 7;

    float acc[2][8][4];
#pragma unroll
    for (int mt = 0; mt < 2; mt++)
#pragma unroll
        for (int nt = 0; nt < 8; nt++)
#pragma unroll
            for (int j = 0; j < 4; j++) acc[mt][nt][j] = 0.f;

    const int T = K >> 6;

    auto load_tile = [&](int stage, int kt) {
#pragma unroll
        for (int i = 0; i < 4; i++) {
            int row = lrow + i * 32;
            int gm = bm + row;
            cp16(sA + (uint32_t)(stage * AW + row * 72 + lq * 8) * 2,
                 A + (size_t)gm * K + kt + lq * 8, (gm < M) ? 16 : 0);
        }
#pragma unroll
        for (int i = 0; i < 4; i++) {
            int row = lrow + i * 32;
            cp16(sB + (uint32_t)(stage * BW + row * 72 + lq * 8) * 2,
                 WT + (size_t)(bn + row) * K + kt + lq * 8, 16);
        }
    };

    load_tile(0, 0);
    CP_COMMIT();

    for (int ti = 0; ti < T; ti++) {
        if (ti + 1 < T) {
            load_tile((ti + 1) & 1, (ti + 1) * 64);
            CP_COMMIT();
            asm volatile("cp.async.wait_group 1;" ::: "memory");
        } else {
            asm volatile("cp.async.wait_group 0;" ::: "memory");
        }
        __syncthreads();

        const uint32_t* Asu = (const uint32_t*)(As + (ti & 1) * AW);
        const uint32_t* Bsu = (const uint32_t*)(Bs + (ti & 1) * BW);
#pragma unroll
        for (int k16 = 0; k16 < 4; k16++) {
            int kw = k16 * 8;
            uint32_t a[2][4];
#pragma unroll
            for (int mt = 0; mt < 2; mt++) {
                int r0 = (wm * 32 + mt * 16 + g) * 36 + kw + t;
                a[mt][0] = Asu[r0];
                a[mt][1] = Asu[r0 + 8 * 36];
                a[mt][2] = Asu[r0 + 4];
                a[mt][3] = Asu[r0 + 8 * 36 + 4];
            }
            uint32_t b[8][2];
#pragma unroll
            for (int nt = 0; nt < 8; nt++) {
                int r0 = (wn * 64 + nt * 8 + g) * 36 + kw + t;
                b[nt][0] = Bsu[r0];
                b[nt][1] = Bsu[r0 + 4];
            }
#pragma unroll
            for (int mt = 0; mt < 2; mt++)
#pragma unroll
                for (int nt = 0; nt < 8; nt++)
                    mma_bf16(acc[mt][nt], a[mt], b[nt]);
        }
        __syncthreads();
    }

    float2 bv[8];
#pragma unroll
    for (int nt = 0; nt < 8; nt++) {
        if (bias) bv[nt] = *(const float2*)(bias + bn + wn * 64 + nt * 8 + 2 * t);
        else bv[nt] = make_float2(0.f, 0.f);
    }

    if (ACT == 2) {
        float* red = (float*)sm;
        float Mx[2][2];
#pragma unroll
        for (int mt = 0; mt < 2; mt++) {
#pragma unroll
            for (int h = 0; h < 2; h++) {
                int gm = bm + wm * 32 + mt * 16 + h * 8 + g;
                float pre = (prescale && gm < M) ? prescale[gm] : 1.f;
                float lm = -1e30f;
#pragma unroll
                for (int nt = 0; nt < 8; nt++) {
                    float ox = acc[mt][nt][2 * h]     * pre + bv[nt].x;
                    float oy = acc[mt][nt][2 * h + 1] * pre + bv[nt].y;
                    acc[mt][nt][2 * h] = ox; acc[mt][nt][2 * h + 1] = oy;
                    lm = fmaxf(lm, fmaxf(ox, oy));
                }
                lm = fmaxf(lm, __shfl_xor_sync(0xffffffffu, lm, 1));
                lm = fmaxf(lm, __shfl_xor_sync(0xffffffffu, lm, 2));
                int r = wm * 32 + mt * 16 + h * 8 + g;
                if (t == 0) red[r * 2 + wn] = lm;
            }
        }
        __syncthreads();
#pragma unroll
        for (int mt = 0; mt < 2; mt++)
#pragma unroll
            for (int h = 0; h < 2; h++) {
                int r = wm * 32 + mt * 16 + h * 8 + g;
                Mx[mt][h] = fmaxf(red[r * 2], red[r * 2 + 1]);
            }
        __syncthreads();
#pragma unroll
        for (int mt = 0; mt < 2; mt++) {
#pragma unroll
            for (int h = 0; h < 2; h++) {
                float ls = 0.f;
#pragma unroll
                for (int nt = 0; nt < 8; nt++) {
                    float ex = expf(acc[mt][nt][2 * h]     - Mx[mt][h]);
                    float ey = expf(acc[mt][nt][2 * h + 1] - Mx[mt][h]);
                    acc[mt][nt][2 * h] = ex; acc[mt][nt][2 * h + 1] = ey;
                    ls += ex + ey;
                }
                ls += __shfl_xor_sync(0xffffffffu, ls, 1);
                ls += __shfl_xor_sync(0xffffffffu, ls, 2);
                int r = wm * 32 + mt * 16 + h * 8 + g;
                if (t == 0) red[r * 2 + wn] = ls;
            }
        }
        __syncthreads();
#pragma unroll
        for (int mt = 0; mt < 2; mt++) {
#pragma unroll
            for (int h = 0; h < 2; h++) {
                int r = wm * 32 + mt * 16 + h * 8 + g;
                float inv = 1.f / (red[r * 2] + red[r * 2 + 1]);
                int gm = bm + wm * 32 + mt * 16 + h * 8 + g;
                if (gm >= M) continue;
#pragma unroll
                for (int nt = 0; nt < 8; nt++) {
                    float2 o = make_float2(acc[mt][nt][2 * h] * inv, acc[mt][nt][2 * h + 1] * inv);
                    *(float2*)((float*)Cout + (size_t)gm * N + bn + wn * 64 + nt * 8 + 2 * t) = o;
                }
            }
        }
        return;
    }

#pragma unroll
    for (int mt = 0; mt < 2; mt++) {
#pragma unroll
        for (int h = 0; h < 2; h++) {
            int gm = bm + wm * 32 + mt * 16 + h * 8 + g;
            if (gm >= M) continue;
            float pre = prescale ? prescale[gm] : 1.f;
            float post = postscale ? postscale[gm] : 1.f;
#pragma unroll
            for (int nt = 0; nt < 8; nt++) {
                float ox = acc[mt][nt][2 * h]     * pre + bv[nt].x;
                float oy = acc[mt][nt][2 * h + 1] * pre + bv[nt].y;
                if (ACT == 1) { ox = tanhf(ox); oy = tanhf(oy); }
                ox *= post; oy *= post;
                size_t off = (size_t)gm * N + bn + wn * 64 + nt * 8 + 2 * t;
                if (OUTT == 2) {
                    *(unsigned short*)((uint8_t*)Cout + off) = f2_to_f8x2(ox, oy);
                } else if (OUTT == 1) {
                    __nv_bfloat162 p = __float22bfloat162_rn(make_float2(ox, oy));
                    *(uint32_t*)((__nv_bfloat16*)Cout + off) = *(uint32_t*)&p;
                } else {
                    *(float2*)((float*)Cout + off) = make_float2(ox, oy);
                }
            }
        }
    }
}

// ---------------- launcher: fork-join dual-stream schedule ----------------
extern "C" void kernel_launch(void* const* d_in, const int* in_sizes, int n_in,
                              void* d_out, int out_size) {
    const float* in_feat = (const float*)d_in[0];
    const int*   src     = (const int*)d_in[1];
    const int*   dst     = (const int*)d_in[2];
    const float* Wc0 = (const float*)d_in[3];
    const float* bc0 = (const float*)d_in[4];
    const float* Wc1 = (const float*)d_in[5];
    const float* bc1 = (const float*)d_in[6];
    const float* Wc2 = (const float*)d_in[7];
    const float* bc2 = (const float*)d_in[8];
    const float* Wr0 = (const float*)d_in[9];
    const float* br0 = (const float*)d_in[10];
    const float* Wr1 = (const float*)d_in[11];
    const float* br1 = (const float*)d_in[12];
    const float* Wr2 = (const float*)d_in[13];
    const float* br2 = (const float*)d_in[14];
    float* out = (float*)d_out;

    float *bufA, *bufB, *bufC, *sout, *sin, *wt;
    cudaGetSymbolAddress((void**)&bufA, g_bufA);
    cudaGetSymbolAddress((void**)&bufB, g_bufB);
    cudaGetSymbolAddress((void**)&bufC, g_bufC);
    cudaGetSymbolAddress((void**)&sout, g_sout);
    cudaGetSymbolAddress((void**)&sin,  g_sin);
    cudaGetSymbolAddress((void**)&wt,   g_wt);

    uint8_t*       xf8  = (uint8_t*)bufA;        // prescaled x, fp8
    __nv_bfloat16* bA16 = (__nv_bfloat16*)bufA;  // conv2 gemm out (h2), MLP r0
    __nv_bfloat16* bB16 = (__nv_bfloat16*)bufB;  // agg outputs / conv3 V
    uint8_t*       h1f8 = (uint8_t*)bufC;        // conv1 gemm out, fp8
    __nv_bfloat16* bC16 = (__nv_bfloat16*)bufC;  // h16 after aggsmax
    __nv_bfloat16* t116 = (__nv_bfloat16*)bufC + (size_t)NN * 128;  // MLP r1
    __nv_bfloat16* WTc0 = (__nv_bfloat16*)(wt + 0 * 65536);
    __nv_bfloat16* WTc1 = (__nv_bfloat16*)(wt + 1 * 65536);
    __nv_bfloat16* WTc2 = (__nv_bfloat16*)(wt + 2 * 65536);
    __nv_bfloat16* WTr0 = (__nv_bfloat16*)(wt + 3 * 65536);
    __nv_bfloat16* WTr1 = (__nv_bfloat16*)(wt + 4 * 65536);
    __nv_bfloat16* WTr2 = (__nv_bfloat16*)(wt + 5 * 65536);

    const int M = NN;
    dim3 g_n((NN + 255) / 256);
    dim3 g_e(4096);
    dim3 g_w((NN * 32 + 255) / 256);
    dim3 gw0((CH0 * 32 + 255) / 256), gw1((CH1 * 32 + 255) / 256);
    const int GT0 = (CH0 + 127) / 128;
    const int GT1 = (CH1 + 127) / 128;

    const int SMEM_GEMM = (2 * 128 * 72 + 2 * 128 * 72) * 2;
    static cudaStream_t s1 = nullptr;
    static cudaEvent_t evRoot, evHist, evPre, evA1, evG1, evA2, evG3, evS0, evR0;
    if (!s1) {
        cudaFuncSetAttribute(k_gemm_bf16<1, 1>, cudaFuncAttributeMaxDynamicSharedMemorySize, SMEM_GEMM);
        cudaFuncSetAttribute(k_gemm_bf16<1, 2>, cudaFuncAttributeMaxDynamicSharedMemorySize, SMEM_GEMM);
        cudaFuncSetAttribute(k_gemm_bf16<0, 1>, cudaFuncAttributeMaxDynamicSharedMemorySize, SMEM_GEMM);
        cudaFuncSetAttribute(k_gemm_bf16<2, 0>, cudaFuncAttributeMaxDynamicSharedMemorySize, SMEM_GEMM);
        cudaStreamCreateWithFlags(&s1, cudaStreamNonBlocking);
        cudaEventCreateWithFlags(&evRoot, cudaEventDisableTiming);
        cudaEventCreateWithFlags(&evHist, cudaEventDisableTiming);
        cudaEventCreateWithFlags(&evPre,  cudaEventDisableTiming);
        cudaEventCreateWithFlags(&evA1,   cudaEventDisableTiming);
        cudaEventCreateWithFlags(&evG1,   cudaEventDisableTiming);
        cudaEventCreateWithFlags(&evA2,   cudaEventDisableTiming);
        cudaEventCreateWithFlags(&evG3,   cudaEventDisableTiming);
        cudaEventCreateWithFlags(&evS0,   cudaEventDisableTiming);
        cudaEventCreateWithFlags(&evR0,   cudaEventDisableTiming);
    }

    // ---- fork: side stream transposes; scales+prescale after hist ----
    cudaEventRecord(evRoot, 0);
    cudaStreamWaitEvent(s1, evRoot, 0);
    k_transpose_all<<<dim3(8, 8, 6), dim3(32, 8), 0, s1>>>(Wc0, Wc1, Wc2, Wr0, Wr1, Wr2,
                                                           WTc0, WTc1, WTc2, WTr0, WTr1, WTr2);
    // main: CSR chain
    k_zero_counts<<<g_n, 256>>>();
    k_hist<<<g_e, 256>>>(src, dst);
    cudaEventRecord(evHist, 0);
    k_scan1<<<SCAN_NB, 1024>>>();
    k_scan2<<<1, 128>>>();
    k_scan3<<<SCAN_NB, 1024>>>();
    k_fill<<<g_e, 256>>>(src, dst);
    // side: scales + prescale (fp8)
    cudaStreamWaitEvent(s1, evHist, 0);
    k_scales<<<g_n, 256, 0, s1>>>();
    k_prescale_f8<<<g_w, 256, 0, s1>>>(in_feat, xf8);
    cudaEventRecord(evPre, s1);
    cudaStreamWaitEvent(0, evPre, 0);

    // ---- conv1: fp8 agg(x) -> bB16 ; gemm -> h1 fp8 ----
    k_agg_f8_128<<<gw0, 256>>>(xf8, bB16, 0, CH0);
    cudaEventRecord(evA1, 0);
    k_agg_f8_128<<<gw1, 256>>>(xf8, bB16, CH0, CH1);
    cudaStreamWaitEvent(s1, evA1, 0);
    k_gemm_bf16<1, 2><<<dim3(GT0, 2), 256, SMEM_GEMM, s1>>>(bB16, WTc0, h1f8, CH0, 128, 256, sin, bc0, sout);
    k_gemm_bf16<1, 2><<<dim3(GT1, 2), 256, SMEM_GEMM>>>(bB16 + (size_t)CH0 * 128, WTc0,
                                                        h1f8 + (size_t)CH0 * 256, CH1, 128, 256,
                                                        sin + CH0, bc0, sout + CH0);
    cudaEventRecord(evG1, s1);
    cudaStreamWaitEvent(0, evG1, 0);

    // ---- conv2: fp8 agg(h1) -> bB16 ; gemm -> bA16 ; conv3 gemm chunked ----
    k_agg_f8_256<<<gw0, 256>>>(h1f8, bB16, 0, CH0);
    cudaEventRecord(evA2, 0);
    k_agg_f8_256<<<gw1, 256>>>(h1f8, bB16, CH0, CH1);
    cudaStreamWaitEvent(s1, evA2, 0);
    k_gemm_bf16<1, 1><<<dim3(GT0, 2), 256, SMEM_GEMM, s1>>>(bB16, WTc1, bA16, CH0, 256, 256, sin, bc1, sout);
    k_gemm_bf16<0, 1><<<dim3(GT0, 1), 256, SMEM_GEMM, s1>>>(bA16, WTc2, bB16, CH0, 256, 128, nullptr, nullptr, nullptr);
    cudaEventRecord(evG3, s1);
    k_gemm_bf16<1, 1><<<dim3(GT1, 2), 256, SMEM_GEMM>>>(bB16 + (size_t)CH0 * 256, WTc1,
                                                        bA16 + (size_t)CH0 * 256, CH1, 256, 256,
                                                        sin + CH0, bc1, sout + CH0);
    k_gemm_bf16<0, 1><<<dim3(GT1, 1), 256, SMEM_GEMM>>>(bA16 + (size_t)CH0 * 256, WTc2,
                                                        bB16 + (size_t)CH0 * 128, CH1, 256, 128, nullptr, nullptr, nullptr);
    cudaStreamWaitEvent(0, evG3, 0);

    // ---- conv3 agg+softmax -> out & h16(bC16); MLP dual-chain ----
    k_agg_smax128<<<gw0, 256>>>(bB16, out, bC16, sin, bc2, 0, CH0);
    cudaEventRecord(evS0, 0);
    k_agg_smax128<<<gw1, 256>>>(bB16, out, bC16, sin, bc2, CH0, CH1);

    cudaStreamWaitEvent(s1, evS0, 0);
    k_gemm_bf16<1, 1><<<dim3(GT0, 2), 256, SMEM_GEMM, s1>>>(bC16, WTr0, bA16, CH0, 128, 256, nullptr, br0, nullptr);
    k_gemm_bf16<1, 1><<<dim3(GT0, 2), 256, SMEM_GEMM, s1>>>(bA16, WTr1, t116, CH0, 256, 256, nullptr, br1, nullptr);
    k_gemm_bf16<2, 0><<<dim3(GT0, 1), 256, SMEM_GEMM, s1>>>(t116, WTr2, out + (size_t)M * 128, CH0, 256, 128, nullptr, br2, nullptr);
    cudaEventRecord(evR0, s1);

    k_gemm_bf16<1, 1><<<dim3(GT1, 2), 256, SMEM_GEMM>>>(bC16 + (size_t)CH0 * 128, WTr0,
                                                        bA16 + (size_t)CH0 * 256, CH1, 128, 256, nullptr, br0, nullptr);
    k_gemm_bf16<1, 1><<<dim3(GT1, 2), 256, SMEM_GEMM>>>(bA16 + (size_t)CH0 * 256, WTr1,
                                                        t116 + (size_t)CH0 * 256, CH1, 256, 256, nullptr, br1, nullptr);
    k_gemm_bf16<2, 0><<<dim3(GT1, 1), 256, SMEM_GEMM>>>(t116 + (size_t)CH0 * 256, WTr2,
                                                        out + (size_t)M * 128 + (size_t)CH0 * 128, CH1, 256, 128, nullptr, br2, nullptr);
    cudaStreamWaitEvent(0, evR0, 0);
}

// round 15
// speedup vs baseline: 1.2899x; 1.2899x over previous
#include <cuda_runtime.h>
#include <cuda_bf16.h>
#include <math.h>
#include <stdint.h>

#define NN 100000
#define EE 1600000
#define SCAN_NB ((NN + 1023) / 1024)
#define NCH 4
#define CSZ 25088   // chunk size (multiple of 128); last chunk = 24736

// ---------------- static scratch ----------------
__device__ float g_bufA[(size_t)NN * 256];
__device__ float g_bufB[(size_t)NN * 256];
__device__ float g_bufC[(size_t)NN * 256];
__device__ float g_sout[NN];
__device__ float g_sin[NN];
__device__ int   g_cnt_out[NN];
__device__ int   g_cnt_in[NN];
__device__ int   g_cursor[NN];
__device__ int   g_row_ptr[NN + 1];
__device__ int   g_csr[EE];
__device__ int   g_blocksum[128];
__device__ float g_wt[6][65536];

// ---------------- graph preprocessing ----------------
__global__ void k_zero_counts() {
    int i = blockIdx.x * blockDim.x + threadIdx.x;
    if (i < NN) { g_cnt_out[i] = 0; g_cnt_in[i] = 0; g_cursor[i] = 0; }
}
__global__ void k_hist(const int* __restrict__ src, const int* __restrict__ dst) {
    int stride = gridDim.x * blockDim.x;
    for (int i = blockIdx.x * blockDim.x + threadIdx.x; i < EE; i += stride) {
        atomicAdd(&g_cnt_out[src[i]], 1);
        atomicAdd(&g_cnt_in[dst[i]], 1);
    }
}
__global__ void k_scan1() {
    __shared__ int wsum[32];
    int b = blockIdx.x, t = threadIdx.x, lane = t & 31, w = t >> 5;
    int idx = b * 1024 + t;
    int x = (idx < NN) ? g_cnt_in[idx] : 0;
#pragma unroll
    for (int off = 1; off < 32; off <<= 1) {
        int y = __shfl_up_sync(0xffffffffu, x, off);
        if (lane >= off) x += y;
    }
    if (lane == 31) wsum[w] = x;
    __syncthreads();
    if (w == 0) {
        int s = wsum[lane];
#pragma unroll
        for (int off = 1; off < 32; off <<= 1) {
            int y = __shfl_up_sync(0xffffffffu, s, off);
            if (lane >= off) s += y;
        }
        wsum[lane] = s;
    }
    __syncthreads();
    int res = ((w > 0) ? wsum[w - 1] : 0) + x;
    if (idx < NN) g_row_ptr[idx + 1] = res;
    if (t == 1023) g_blocksum[b] = res;
}
__global__ void k_scan2() {
    __shared__ int wsum[4];
    int t = threadIdx.x, lane = t & 31, w = t >> 5;
    int v = (t < SCAN_NB) ? g_blocksum[t] : 0;
    int x = v;
#pragma unroll
    for (int off = 1; off < 32; off <<= 1) {
        int y = __shfl_up_sync(0xffffffffu, x, off);
        if (lane >= off) x += y;
    }
    if (lane == 31) wsum[w] = x;
    __syncthreads();
    if (t == 0) {
        int c = 0;
        for (int i = 0; i < 4; i++) { int tmp = wsum[i]; wsum[i] = c; c += tmp; }
    }
    __syncthreads();
    if (t < SCAN_NB) g_blocksum[t] = wsum[w] + x - v;
}
__global__ void k_scan3() {
    int b = blockIdx.x, t = threadIdx.x;
    int idx = b * 1024 + t;
    if (idx == 0) g_row_ptr[0] = 0;
    if (idx < NN && b > 0) g_row_ptr[idx + 1] += g_blocksum[b];
}
__global__ void k_fill(const int* __restrict__ src, const int* __restrict__ dst) {
    int stride = gridDim.x * blockDim.x;
    for (int i = blockIdx.x * blockDim.x + threadIdx.x; i < EE; i += stride) {
        int d = dst[i];
        int pos = g_row_ptr[d] + atomicAdd(&g_cursor[d], 1);
        g_csr[pos] = src[i];
    }
}
__global__ void k_scales() {
    int i = blockIdx.x * blockDim.x + threadIdx.x;
    if (i < NN) {
        g_sout[i] = rsqrtf(fmaxf((float)g_cnt_out[i], 1.f));
        g_sin[i]  = rsqrtf(fmaxf((float)g_cnt_in[i], 1.f));
    }
}

__global__ void k_transpose_all(
    const float* W0, const float* W1, const float* W2,
    const float* W3, const float* W4, const float* W5,
    __nv_bfloat16* T0, __nv_bfloat16* T1, __nv_bfloat16* T2,
    __nv_bfloat16* T3, __nv_bfloat16* T4, __nv_bfloat16* T5) {
    __shared__ float t[32][33];
    const float* W; __nv_bfloat16* WT; int K, N;
    switch (blockIdx.z) {
        case 0: W = W0; WT = T0; K = 128; N = 256; break;
        case 1: W = W1; WT = T1; K = 256; N = 256; break;
        case 2: W = W2; WT = T2; K = 256; N = 128; break;
        case 3: W = W3; WT = T3; K = 128; N = 256; break;
        case 4: W = W4; WT = T4; K = 256; N = 256; break;
        default: W = W5; WT = T5; K = 256; N = 128; break;
    }
    int k0 = blockIdx.x * 32, n0 = blockIdx.y * 32;
    if (k0 >= K || n0 >= N) return;
    int x = threadIdx.x, y = threadIdx.y;
    for (int i = 0; i < 32; i += 8) {
        int k = k0 + y + i, n = n0 + x;
        t[y + i][x] = (k < K && n < N) ? W[(size_t)k * N + n] : 0.f;
    }
    __syncthreads();
    for (int i = 0; i < 32; i += 8) {
        int n = n0 + y + i, k = k0 + x;
        if (n < N && k < K) WT[(size_t)n * K + k] = __float2bfloat16(t[x][y + i]);
    }
}

__global__ void k_prescale(const float* __restrict__ x, __nv_bfloat16* __restrict__ o) {
    int i = blockIdx.x * blockDim.x + threadIdx.x;
    if (i >= NN * 32) return;
    int m = i >> 5;
    float s = g_sout[m];
    float4 v = ((const float4*)x)[i];
    uint2 r;
    __nv_bfloat162 p0 = __float22bfloat162_rn(make_float2(v.x * s, v.y * s));
    __nv_bfloat162 p1 = __float22bfloat162_rn(make_float2(v.z * s, v.w * s));
    r.x = *(uint32_t*)&p0; r.y = *(uint32_t*)&p1;
    ((uint2*)o)[i] = r;
}

// ---------------- aggregation helpers ----------------
__device__ __forceinline__ void acc_add2(float4& a, uint2 v) {
    __nv_bfloat162 p0 = *(__nv_bfloat162*)&v.x;
    __nv_bfloat162 p1 = *(__nv_bfloat162*)&v.y;
    a.x += __low2float(p0); a.y += __high2float(p0);
    a.z += __low2float(p1); a.w += __high2float(p1);
}
__device__ __forceinline__ float4 agg128_core(const __nv_bfloat16* __restrict__ x,
                                              int s0, int s1, int lane) {
    float4 a0 = make_float4(0.f, 0.f, 0.f, 0.f);
    float4 a1 = make_float4(0.f, 0.f, 0.f, 0.f);
    float4 a2 = make_float4(0.f, 0.f, 0.f, 0.f);
    float4 a3 = make_float4(0.f, 0.f, 0.f, 0.f);
    for (int base = s0; base < s1; base += 32) {
        int cnt = min(32, s1 - base);
        int myidx = (lane < cnt) ? g_csr[base + lane] : 0;
        int e = 0;
        for (; e + 4 <= cnt; e += 4) {
            int sa = __shfl_sync(0xffffffffu, myidx, e);
            int sb = __shfl_sync(0xffffffffu, myidx, e + 1);
            int sc = __shfl_sync(0xffffffffu, myidx, e + 2);
            int sd = __shfl_sync(0xffffffffu, myidx, e + 3);
            uint2 va = ((const uint2*)(x + (size_t)sa * 128))[lane];
            uint2 vb = ((const uint2*)(x + (size_t)sb * 128))[lane];
            uint2 vc = ((const uint2*)(x + (size_t)sc * 128))[lane];
            uint2 vd = ((const uint2*)(x + (size_t)sd * 128))[lane];
            acc_add2(a0, va); acc_add2(a1, vb); acc_add2(a2, vc); acc_add2(a3, vd);
        }
        for (; e < cnt; e++) {
            int sa = __shfl_sync(0xffffffffu, myidx, e);
            uint2 va = ((const uint2*)(x + (size_t)sa * 128))[lane];
            acc_add2(a0, va);
        }
    }
    return make_float4(a0.x + a1.x + a2.x + a3.x, a0.y + a1.y + a2.y + a3.y,
                       a0.z + a1.z + a2.z + a3.z, a0.w + a1.w + a2.w + a3.w);
}

template <int D, int OUTB>
__global__ void k_agg_b16(const __nv_bfloat16* __restrict__ x, void* __restrict__ out,
                          int n0, int ncnt) {
    int wloc = (blockIdx.x * blockDim.x + threadIdx.x) >> 5;
    int lane = threadIdx.x & 31;
    if (wloc >= ncnt) return;
    int node = n0 + wloc;
    int s0 = g_row_ptr[node], s1 = g_row_ptr[node + 1];

    if (D == 128) {
        float4 acc = agg128_core(x, s0, s1, lane);
        if (OUTB) {
            uint2 r;
            __nv_bfloat162 p0 = __float22bfloat162_rn(make_float2(acc.x, acc.y));
            __nv_bfloat162 p1 = __float22bfloat162_rn(make_float2(acc.z, acc.w));
            r.x = *(uint32_t*)&p0; r.y = *(uint32_t*)&p1;
            ((uint2*)out)[(size_t)node * 32 + lane] = r;
        } else {
            ((float4*)out)[(size_t)node * 32 + lane] = acc;
        }
    } else {  // D == 256
        float a0[8], a1[8];
#pragma unroll
        for (int j = 0; j < 8; j++) { a0[j] = 0.f; a1[j] = 0.f; }
        for (int base = s0; base < s1; base += 32) {
            int cnt = min(32, s1 - base);
            int myidx = (lane < cnt) ? g_csr[base + lane] : 0;
            int e = 0;
            for (; e + 2 <= cnt; e += 2) {
                int sa = __shfl_sync(0xffffffffu, myidx, e);
                int sb = __shfl_sync(0xffffffffu, myidx, e + 1);
                uint4 va = ((const uint4*)(x + (size_t)sa * 256))[lane];
                uint4 vb = ((const uint4*)(x + (size_t)sb * 256))[lane];
                {
                    __nv_bfloat162 p0 = *(__nv_bfloat162*)&va.x, p1 = *(__nv_bfloat162*)&va.y;
                    __nv_bfloat162 p2 = *(__nv_bfloat162*)&va.z, p3 = *(__nv_bfloat162*)&va.w;
                    a0[0] += __low2float(p0); a0[1] += __high2float(p0);
                    a0[2] += __low2float(p1); a0[3] += __high2float(p1);
                    a0[4] += __low2float(p2); a0[5] += __high2float(p2);
                    a0[6] += __low2float(p3); a0[7] += __high2float(p3);
                }
                {
                    __nv_bfloat162 p0 = *(__nv_bfloat162*)&vb.x, p1 = *(__nv_bfloat162*)&vb.y;
                    __nv_bfloat162 p2 = *(__nv_bfloat162*)&vb.z, p3 = *(__nv_bfloat162*)&vb.w;
                    a1[0] += __low2float(p0); a1[1] += __high2float(p0);
                    a1[2] += __low2float(p1); a1[3] += __high2float(p1);
                    a1[4] += __low2float(p2); a1[5] += __high2float(p2);
                    a1[6] += __low2float(p3); a1[7] += __high2float(p3);
                }
            }
            if (e < cnt) {
                int sa = __shfl_sync(0xffffffffu, myidx, e);
                uint4 va = ((const uint4*)(x + (size_t)sa * 256))[lane];
                __nv_bfloat162 p0 = *(__nv_bfloat162*)&va.x, p1 = *(__nv_bfloat162*)&va.y;
                __nv_bfloat162 p2 = *(__nv_bfloat162*)&va.z, p3 = *(__nv_bfloat162*)&va.w;
                a0[0] += __low2float(p0); a0[1] += __high2float(p0);
                a0[2] += __low2float(p1); a0[3] += __high2float(p1);
                a0[4] += __low2float(p2); a0[5] += __high2float(p2);
                a0[6] += __low2float(p3); a0[7] += __high2float(p3);
            }
        }
        uint4 r;
        __nv_bfloat162 q0 = __float22bfloat162_rn(make_float2(a0[0] + a1[0], a0[1] + a1[1]));
        __nv_bfloat162 q1 = __float22bfloat162_rn(make_float2(a0[2] + a1[2], a0[3] + a1[3]));
        __nv_bfloat162 q2 = __float22bfloat162_rn(make_float2(a0[4] + a1[4], a0[5] + a1[5]));
        __nv_bfloat162 q3 = __float22bfloat162_rn(make_float2(a0[6] + a1[6], a0[7] + a1[7]));
        r.x = *(uint32_t*)&q0; r.y = *(uint32_t*)&q1;
        r.z = *(uint32_t*)&q2; r.w = *(uint32_t*)&q3;
        ((uint4*)out)[(size_t)node * 32 + lane] = r;
    }
}

__global__ void k_agg_smax128(const __nv_bfloat16* __restrict__ x,
                              float* __restrict__ out, __nv_bfloat16* __restrict__ outb,
                              const float* __restrict__ rowscale, const float* __restrict__ bias,
                              int n0, int ncnt) {
    int wloc = (blockIdx.x * blockDim.x + threadIdx.x) >> 5;
    int lane = threadIdx.x & 31;
    if (wloc >= ncnt) return;
    int node = n0 + wloc;
    int s0 = g_row_ptr[node], s1 = g_row_ptr[node + 1];
    float4 v = agg128_core(x, s0, s1, lane);
    float rs = rowscale[node];
    float4 b = ((const float4*)bias)[lane];
    v.x = v.x * rs + b.x; v.y = v.y * rs + b.y;
    v.z = v.z * rs + b.z; v.w = v.w * rs + b.w;
    float m = fmaxf(fmaxf(v.x, v.y), fmaxf(v.z, v.w));
#pragma unroll
    for (int off = 16; off > 0; off >>= 1) m = fmaxf(m, __shfl_xor_sync(0xffffffffu, m, off));
    v.x = expf(v.x - m); v.y = expf(v.y - m);
    v.z = expf(v.z - m); v.w = expf(v.w - m);
    float s = v.x + v.y + v.z + v.w;
#pragma unroll
    for (int off = 16; off > 0; off >>= 1) s += __shfl_xor_sync(0xffffffffu, s, off);
    float inv = 1.f / s;
    v.x *= inv; v.y *= inv; v.z *= inv; v.w *= inv;
    ((float4*)out)[(size_t)node * 32 + lane] = v;
    uint2 r;
    __nv_bfloat162 p0 = __float22bfloat162_rn(make_float2(v.x, v.y));
    __nv_bfloat162 p1 = __float22bfloat162_rn(make_float2(v.z, v.w));
    r.x = *(uint32_t*)&p0; r.y = *(uint32_t*)&p1;
    ((uint2*)outb)[(size_t)node * 32 + lane] = r;
}

// ---------------- bf16 tensor-core GEMM, BN=128, cp.async 2-stage ----------------
__device__ __forceinline__ void mma_bf16(float* d, const uint32_t* a, const uint32_t* b) {
    asm volatile(
        "mma.sync.aligned.m16n8k16.row.col.f32.bf16.bf16.f32 "
        "{%0,%1,%2,%3}, {%4,%5,%6,%7}, {%8,%9}, {%0,%1,%2,%3};"
        : "+f"(d[0]), "+f"(d[1]), "+f"(d[2]), "+f"(d[3])
        : "r"(a[0]), "r"(a[1]), "r"(a[2]), "r"(a[3]), "r"(b[0]), "r"(b[1]));
}
__device__ __forceinline__ void cp16(uint32_t dst, const void* src, int sz) {
    asm volatile("cp.async.cg.shared.global [%0], [%1], 16, %2;" :: "r"(dst), "l"(src), "r"(sz) : "memory");
}
#define CP_COMMIT() asm volatile("cp.async.commit_group;" ::: "memory")

// ACT: 0 none, 1 tanh, 2 row-softmax (N==128, gridDim.y==1, OUTB=0)
template <int ACT, int OUTB>
__global__ void __launch_bounds__(256, 2)
k_gemm_bf16(const __nv_bfloat16* __restrict__ A, const __nv_bfloat16* __restrict__ WT,
            void* __restrict__ Cout, int M, int K, int N,
            const float* __restrict__ prescale, const float* __restrict__ bias,
            const float* __restrict__ postscale) {
    extern __shared__ __nv_bfloat16 sm[];
    constexpr int AW = 128 * 72;
    constexpr int BW = 128 * 72;
    __nv_bfloat16* As = sm;
    __nv_bfloat16* Bs = sm + 2 * AW;
    uint32_t sA = (uint32_t)__cvta_generic_to_shared(As);
    uint32_t sB = (uint32_t)__cvta_generic_to_shared(Bs);

    int tid = threadIdx.x;
    int warp = tid >> 5, lane = tid & 31;
    int g = lane >> 2, t = lane & 3;
    int wm = warp >> 1, wn = warp & 1;
    int bm = blockIdx.x * 128, bn = blockIdx.y * 128;
    int lrow = tid >> 3, lq = tid & 7;

    float acc[2][8][4];
#pragma unroll
    for (int mt = 0; mt < 2; mt++)
#pragma unroll
        for (int nt = 0; nt < 8; nt++)
#pragma unroll
            for (int j = 0; j < 4; j++) acc[mt][nt][j] = 0.f;

    const int T = K >> 6;

    auto load_tile = [&](int stage, int kt) {
#pragma unroll
        for (int i = 0; i < 4; i++) {
            int row = lrow + i * 32;
            int gm = bm + row;
            cp16(sA + (uint32_t)(stage * AW + row * 72 + lq * 8) * 2,
                 A + (size_t)gm * K + kt + lq * 8, (gm < M) ? 16 : 0);
        }
#pragma unroll
        for (int i = 0; i < 4; i++) {
            int row = lrow + i * 32;
            cp16(sB + (uint32_t)(stage * BW + row * 72 + lq * 8) * 2,
                 WT + (size_t)(bn + row) * K + kt + lq * 8, 16);
        }
    };

    load_tile(0, 0);
    CP_COMMIT();

    for (int ti = 0; ti < T; ti++) {
        if (ti + 1 < T) {
            load_tile((ti + 1) & 1, (ti + 1) * 64);
            CP_COMMIT();
            asm volatile("cp.async.wait_group 1;" ::: "memory");
        } else {
            asm volatile("cp.async.wait_group 0;" ::: "memory");
        }
        __syncthreads();

        const uint32_t* Asu = (const uint32_t*)(As + (ti & 1) * AW);
        const uint32_t* Bsu = (const uint32_t*)(Bs + (ti & 1) * BW);
#pragma unroll
        for (int k16 = 0; k16 < 4; k16++) {
            int kw = k16 * 8;
            uint32_t a[2][4];
#pragma unroll
            for (int mt = 0; mt < 2; mt++) {
                int r0 = (wm * 32 + mt * 16 + g) * 36 + kw + t;
                a[mt][0] = Asu[r0];
                a[mt][1] = Asu[r0 + 8 * 36];
                a[mt][2] = Asu[r0 + 4];
                a[mt][3] = Asu[r0 + 8 * 36 + 4];
            }
            uint32_t b[8][2];
#pragma unroll
            for (int nt = 0; nt < 8; nt++) {
                int r0 = (wn * 64 + nt * 8 + g) * 36 + kw + t;
                b[nt][0] = Bsu[r0];
                b[nt][1] = Bsu[r0 + 4];
            }
#pragma unroll
            for (int mt = 0; mt < 2; mt++)
#pragma unroll
                for (int nt = 0; nt < 8; nt++)
                    mma_bf16(acc[mt][nt], a[mt], b[nt]);
        }
        __syncthreads();
    }

    float2 bv[8];
#pragma unroll
    for (int nt = 0; nt < 8; nt++) {
        if (bias) bv[nt] = *(const float2*)(bias + bn + wn * 64 + nt * 8 + 2 * t);
        else bv[nt] = make_float2(0.f, 0.f);
    }

    if (ACT == 2) {
        float* red = (float*)sm;
        float Mx[2][2];
#pragma unroll
        for (int mt = 0; mt < 2; mt++) {
#pragma unroll
            for (int h = 0; h < 2; h++) {
                int gm = bm + wm * 32 + mt * 16 + h * 8 + g;
                float pre = (prescale && gm < M) ? prescale[gm] : 1.f;
                float lm = -1e30f;
#pragma unroll
                for (int nt = 0; nt < 8; nt++) {
                    float ox = acc[mt][nt][2 * h]     * pre + bv[nt].x;
                    float oy = acc[mt][nt][2 * h + 1] * pre + bv[nt].y;
                    acc[mt][nt][2 * h] = ox; acc[mt][nt][2 * h + 1] = oy;
                    lm = fmaxf(lm, fmaxf(ox, oy));
                }
                lm = fmaxf(lm, __shfl_xor_sync(0xffffffffu, lm, 1));
                lm = fmaxf(lm, __shfl_xor_sync(0xffffffffu, lm, 2));
                int r = wm * 32 + mt * 16 + h * 8 + g;
                if (t == 0) red[r * 2 + wn] = lm;
            }
        }
        __syncthreads();
#pragma unroll
        for (int mt = 0; mt < 2; mt++)
#pragma unroll
            for (int h = 0; h < 2; h++) {
                int r = wm * 32 + mt * 16 + h * 8 + g;
                Mx[mt][h] = fmaxf(red[r * 2], red[r * 2 + 1]);
            }
        __syncthreads();
#pragma unroll
        for (int mt = 0; mt < 2; mt++) {
#pragma unroll
            for (int h = 0; h < 2; h++) {
                float ls = 0.f;
#pragma unroll
                for (int nt = 0; nt < 8; nt++) {
                    float ex = expf(acc[mt][nt][2 * h]     - Mx[mt][h]);
                    float ey = expf(acc[mt][nt][2 * h + 1] - Mx[mt][h]);
                    acc[mt][nt][2 * h] = ex; acc[mt][nt][2 * h + 1] = ey;
                    ls += ex + ey;
                }
                ls += __shfl_xor_sync(0xffffffffu, ls, 1);
                ls += __shfl_xor_sync(0xffffffffu, ls, 2);
                int r = wm * 32 + mt * 16 + h * 8 + g;
                if (t == 0) red[r * 2 + wn] = ls;
            }
        }
        __syncthreads();
#pragma unroll
        for (int mt = 0; mt < 2; mt++) {
#pragma unroll
            for (int h = 0; h < 2; h++) {
                int r = wm * 32 + mt * 16 + h * 8 + g;
                float inv = 1.f / (red[r * 2] + red[r * 2 + 1]);
                int gm = bm + wm * 32 + mt * 16 + h * 8 + g;
                if (gm >= M) continue;
#pragma unroll
                for (int nt = 0; nt < 8; nt++) {
                    float2 o = make_float2(acc[mt][nt][2 * h] * inv, acc[mt][nt][2 * h + 1] * inv);
                    *(float2*)((float*)Cout + (size_t)gm * N + bn + wn * 64 + nt * 8 + 2 * t) = o;
                }
            }
        }
        return;
    }

#pragma unroll
    for (int mt = 0; mt < 2; mt++) {
#pragma unroll
        for (int h = 0; h < 2; h++) {
            int gm = bm + wm * 32 + mt * 16 + h * 8 + g;
            if (gm >= M) continue;
            float pre = prescale ? prescale[gm] : 1.f;
            float post = postscale ? postscale[gm] : 1.f;
#pragma unroll
            for (int nt = 0; nt < 8; nt++) {
                float ox = acc[mt][nt][2 * h]     * pre + bv[nt].x;
                float oy = acc[mt][nt][2 * h + 1] * pre + bv[nt].y;
                if (ACT == 1) { ox = tanhf(ox); oy = tanhf(oy); }
                ox *= post; oy *= post;
                size_t off = (size_t)gm * N + bn + wn * 64 + nt * 8 + 2 * t;
                if (OUTB) {
                    __nv_bfloat162 p = __float22bfloat162_rn(make_float2(ox, oy));
                    *(uint32_t*)((__nv_bfloat16*)Cout + off) = *(uint32_t*)&p;
                } else {
                    *(float2*)((float*)Cout + off) = make_float2(ox, oy);
                }
            }
        }
    }
}

// ---------------- launcher: fork-join dual-stream, 4-chunk layer pipeline ----------------
extern "C" void kernel_launch(void* const* d_in, const int* in_sizes, int n_in,
                              void* d_out, int out_size) {
    const float* in_feat = (const float*)d_in[0];
    const int*   src     = (const int*)d_in[1];
    const int*   dst     = (const int*)d_in[2];
    const float* Wc0 = (const float*)d_in[3];
    const float* bc0 = (const float*)d_in[4];
    const float* Wc1 = (const float*)d_in[5];
    const float* bc1 = (const float*)d_in[6];
    const float* Wc2 = (const float*)d_in[7];
    const float* bc2 = (const float*)d_in[8];
    const float* Wr0 = (const float*)d_in[9];
    const float* br0 = (const float*)d_in[10];
    const float* Wr1 = (const float*)d_in[11];
    const float* br1 = (const float*)d_in[12];
    const float* Wr2 = (const float*)d_in[13];
    const float* br2 = (const float*)d_in[14];
    float* out = (float*)d_out;

    float *bufA, *bufB, *bufC, *sout, *sin, *wt;
    cudaGetSymbolAddress((void**)&bufA, g_bufA);
    cudaGetSymbolAddress((void**)&bufB, g_bufB);
    cudaGetSymbolAddress((void**)&bufC, g_bufC);
    cudaGetSymbolAddress((void**)&sout, g_sout);
    cudaGetSymbolAddress((void**)&sin,  g_sin);
    cudaGetSymbolAddress((void**)&wt,   g_wt);

    __nv_bfloat16* bA16 = (__nv_bfloat16*)bufA;
    __nv_bfloat16* bB16 = (__nv_bfloat16*)bufB;
    __nv_bfloat16* bC16 = (__nv_bfloat16*)bufC;
    __nv_bfloat16* t116 = (__nv_bfloat16*)bufC + (size_t)NN * 128;
    __nv_bfloat16* WTc0 = (__nv_bfloat16*)(wt + 0 * 65536);
    __nv_bfloat16* WTc1 = (__nv_bfloat16*)(wt + 1 * 65536);
    __nv_bfloat16* WTc2 = (__nv_bfloat16*)(wt + 2 * 65536);
    __nv_bfloat16* WTr0 = (__nv_bfloat16*)(wt + 3 * 65536);
    __nv_bfloat16* WTr1 = (__nv_bfloat16*)(wt + 4 * 65536);
    __nv_bfloat16* WTr2 = (__nv_bfloat16*)(wt + 5 * 65536);

    const int M = NN;
    // chunk tables
    int off_[NCH], cnt_[NCH];
    for (int i = 0; i < NCH; i++) {
        off_[i] = i * CSZ;
        cnt_[i] = (i == NCH - 1) ? (NN - i * CSZ) : CSZ;
    }
    const int H0 = 2 * CSZ;            // half split for conv3/MLP (= 50176)
    const int H1 = NN - H0;

    dim3 g_n((NN + 255) / 256);
    dim3 g_e(4096);
    dim3 g_w((NN * 32 + 255) / 256);

    const int SMEM_GEMM = (2 * 128 * 72 + 2 * 128 * 72) * 2;
    static cudaStream_t s1 = nullptr;
    static cudaEvent_t evRoot, evHist, evPre, evG1, evG3, evS0, evR0;
    static cudaEvent_t evA[NCH], evB[NCH];
    if (!s1) {
        cudaFuncSetAttribute(k_gemm_bf16<1, 1>, cudaFuncAttributeMaxDynamicSharedMemorySize, SMEM_GEMM);
        cudaFuncSetAttribute(k_gemm_bf16<0, 1>, cudaFuncAttributeMaxDynamicSharedMemorySize, SMEM_GEMM);
        cudaFuncSetAttribute(k_gemm_bf16<2, 0>, cudaFuncAttributeMaxDynamicSharedMemorySize, SMEM_GEMM);
        cudaStreamCreateWithFlags(&s1, cudaStreamNonBlocking);
        cudaEventCreateWithFlags(&evRoot, cudaEventDisableTiming);
        cudaEventCreateWithFlags(&evHist, cudaEventDisableTiming);
        cudaEventCreateWithFlags(&evPre,  cudaEventDisableTiming);
        cudaEventCreateWithFlags(&evG1,   cudaEventDisableTiming);
        cudaEventCreateWithFlags(&evG3,   cudaEventDisableTiming);
        cudaEventCreateWithFlags(&evS0,   cudaEventDisableTiming);
        cudaEventCreateWithFlags(&evR0,   cudaEventDisableTiming);
        for (int i = 0; i < NCH; i++) {
            cudaEventCreateWithFlags(&evA[i], cudaEventDisableTiming);
            cudaEventCreateWithFlags(&evB[i], cudaEventDisableTiming);
        }
    }

    // ---- fork: side stream transposes; scales+prescale after hist ----
    cudaEventRecord(evRoot, 0);
    cudaStreamWaitEvent(s1, evRoot, 0);
    k_transpose_all<<<dim3(8, 8, 6), dim3(32, 8), 0, s1>>>(Wc0, Wc1, Wc2, Wr0, Wr1, Wr2,
                                                           WTc0, WTc1, WTc2, WTr0, WTr1, WTr2);
    // main: CSR chain
    k_zero_counts<<<g_n, 256>>>();
    k_hist<<<g_e, 256>>>(src, dst);
    cudaEventRecord(evHist, 0);
    k_scan1<<<SCAN_NB, 1024>>>();
    k_scan2<<<1, 128>>>();
    k_scan3<<<SCAN_NB, 1024>>>();
    k_fill<<<g_e, 256>>>(src, dst);
    // side: scales + prescale
    cudaStreamWaitEvent(s1, evHist, 0);
    k_scales<<<g_n, 256, 0, s1>>>();
    k_prescale<<<g_w, 256, 0, s1>>>(in_feat, bA16);
    cudaEventRecord(evPre, s1);
    cudaStreamWaitEvent(0, evPre, 0);

    // ---- conv1: 4-chunk pipeline — aggs on main, gemms chase on s1 ----
    for (int i = 0; i < NCH; i++) {
        dim3 gw((cnt_[i] * 32 + 255) / 256);
        k_agg_b16<128, 1><<<gw, 256>>>(bA16, bB16, off_[i], cnt_[i]);
        cudaEventRecord(evA[i], 0);
        cudaStreamWaitEvent(s1, evA[i], 0);
        int GTc = (cnt_[i] + 127) / 128;
        k_gemm_bf16<1, 1><<<dim3(GTc, 2), 256, SMEM_GEMM, s1>>>(
            bB16 + (size_t)off_[i] * 128, WTc0, bC16 + (size_t)off_[i] * 256,
            cnt_[i], 128, 256, sin + off_[i], bc0, sout + off_[i]);
    }
    cudaEventRecord(evG1, s1);
    cudaStreamWaitEvent(0, evG1, 0);

    // ---- conv2: 4-chunk pipeline ----
    for (int i = 0; i < NCH; i++) {
        dim3 gw((cnt_[i] * 32 + 255) / 256);
        k_agg_b16<256, 1><<<gw, 256>>>(bC16, bB16, off_[i], cnt_[i]);
        cudaEventRecord(evB[i], 0);
        cudaStreamWaitEvent(s1, evB[i], 0);
        int GTc = (cnt_[i] + 127) / 128;
        k_gemm_bf16<1, 1><<<dim3(GTc, 2), 256, SMEM_GEMM, s1>>>(
            bB16 + (size_t)off_[i] * 256, WTc1, bA16 + (size_t)off_[i] * 256,
            cnt_[i], 256, 256, sin + off_[i], bc1, sout + off_[i]);
        // conv3 gemm for this chunk right behind on s1 (reads only chunk rows of bA16)
        k_gemm_bf16<0, 1><<<dim3(GTc, 1), 256, SMEM_GEMM, s1>>>(
            bA16 + (size_t)off_[i] * 256, WTc2, bB16 + (size_t)off_[i] * 128,
            cnt_[i], 256, 128, nullptr, nullptr, nullptr);
    }
    cudaEventRecord(evG3, s1);
    cudaStreamWaitEvent(0, evG3, 0);

    // ---- conv3 agg+softmax -> out & h16(bC16); MLP dual-chain (2 halves) ----
    {
        dim3 gwh0((H0 * 32 + 255) / 256), gwh1((H1 * 32 + 255) / 256);
        k_agg_smax128<<<gwh0, 256>>>(bB16, out, bC16, sin, bc2, 0, H0);
        cudaEventRecord(evS0, 0);
        k_agg_smax128<<<gwh1, 256>>>(bB16, out, bC16, sin, bc2, H0, H1);

        const int GTA = (H0 + 127) / 128, GTB = (H1 + 127) / 128;
        cudaStreamWaitEvent(s1, evS0, 0);
        k_gemm_bf16<1, 1><<<dim3(GTA, 2), 256, SMEM_GEMM, s1>>>(bC16, WTr0, bA16, H0, 128, 256, nullptr, br0, nullptr);
        k_gemm_bf16<1, 1><<<dim3(GTA, 2), 256, SMEM_GEMM, s1>>>(bA16, WTr1, t116, H0, 256, 256, nullptr, br1, nullptr);
        k_gemm_bf16<2, 0><<<dim3(GTA, 1), 256, SMEM_GEMM, s1>>>(t116, WTr2, out + (size_t)M * 128, H0, 256, 128, nullptr, br2, nullptr);
        cudaEventRecord(evR0, s1);

        k_gemm_bf16<1, 1><<<dim3(GTB, 2), 256, SMEM_GEMM>>>(bC16 + (size_t)H0 * 128, WTr0,
                                                            bA16 + (size_t)H0 * 256, H1, 128, 256, nullptr, br0, nullptr);
        k_gemm_bf16<1, 1><<<dim3(GTB, 2), 256, SMEM_GEMM>>>(bA16 + (size_t)H0 * 256, WTr1,
                                                            t116 + (size_t)H0 * 256, H1, 256, 256, nullptr, br1, nullptr);
        k_gemm_bf16<2, 0><<<dim3(GTB, 1), 256, SMEM_GEMM>>>(t116 + (size_t)H0 * 256, WTr2,
                                                            out + (size_t)M * 128 + (size_t)H0 * 128, H1, 256, 128, nullptr, br2, nullptr);
        cudaStreamWaitEvent(0, evR0, 0);
    }
}